// round 1
// baseline (speedup 1.0000x reference)
#include <cuda_runtime.h>

// Problem constants (fixed by the reference)
#define NU   100000
#define NI   50000
#define NTOT 150000
#define D    64
#define DV4  16           // 64 floats = 16 float4
#define BATCH 4096
#define WD   1e-4f

// Scratch (device globals: allocation-free)
__device__ float4 g_buf0[NTOT * DV4];   // 38.4 MB
__device__ float4 g_buf1[NTOT * DV4];   // 38.4 MB
__device__ float4 g_sel[3 * BATCH * DV4]; // gathered light_out accumulator (3 MB)

// ---------------------------------------------------------------------------
// init: g_buf0 = concat(user_emb, item_emb); zero d_out
// ---------------------------------------------------------------------------
__global__ void k_init(const float4* __restrict__ ue, const float4* __restrict__ ie,
                       float* __restrict__ out) {
    int i = blockIdx.x * blockDim.x + threadIdx.x;
    if (i == 0) out[0] = 0.0f;
    const int total = NTOT * DV4;
    const int stride = gridDim.x * blockDim.x;
    for (; i < total; i += stride) {
        g_buf0[i] = (i < NU * DV4) ? ue[i] : ie[i - NU * DV4];
    }
}

// ---------------------------------------------------------------------------
// zero one ping-pong buffer (which: 0 -> zero g_buf1, 1 -> zero g_buf0)
// matches k_spmm's dst selection below
// ---------------------------------------------------------------------------
__global__ void k_zero(int which) {
    float4* dst = which ? g_buf0 : g_buf1;
    int i = blockIdx.x * blockDim.x + threadIdx.x;
    const int total = NTOT * DV4;
    const int stride = gridDim.x * blockDim.x;
    float4 z = make_float4(0.f, 0.f, 0.f, 0.f);
    for (; i < total; i += stride) dst[i] = z;
}

// ---------------------------------------------------------------------------
// SpMM: dst[rows[e]] += vals[e] * src[cols[e]]   (16 lanes per edge, red.v4)
// which==0: src=g_buf0, dst=g_buf1 ; which==1: src=g_buf1, dst=g_buf0
// ---------------------------------------------------------------------------
__global__ void k_spmm(const int* __restrict__ rows, const int* __restrict__ cols,
                       const float* __restrict__ vals, int nnz, int which) {
    const float4* __restrict__ src = which ? g_buf1 : g_buf0;
    float4* dst = which ? g_buf0 : g_buf1;

    int gid = blockIdx.x * blockDim.x + threadIdx.x;
    int lane16 = gid & 15;
    int group  = gid >> 4;
    int ngroups = (gridDim.x * blockDim.x) >> 4;

    for (int e = group; e < nnz; e += ngroups) {
        int   r = rows[e];
        int   c = cols[e];
        float v = vals[e];
        float4 x = src[c * DV4 + lane16];
        float4 y;
        y.x = x.x * v; y.y = x.y * v; y.z = x.z * v; y.w = x.w * v;
        float4* p = dst + r * DV4 + lane16;
        asm volatile("red.global.add.v4.f32 [%0], {%1, %2, %3, %4};"
                     :: "l"(p), "f"(y.x), "f"(y.y), "f"(y.z), "f"(y.w)
                     : "memory");
    }
}

// ---------------------------------------------------------------------------
// selection-buffer init: g_sel = all_e at rows {users, NU+pos, NU+neg}
// (read straight from the original embedding inputs)
// ---------------------------------------------------------------------------
__global__ void k_sel_init(const float4* __restrict__ ue, const float4* __restrict__ ie,
                           const int* __restrict__ users, const int* __restrict__ pos,
                           const int* __restrict__ neg) {
    int i = blockIdx.x * blockDim.x + threadIdx.x;
    if (i >= 3 * BATCH * DV4) return;
    int lane = i & 15;
    int j = i >> 4;            // [0, 3*BATCH)
    int kind = j / BATCH;
    int b = j - kind * BATCH;
    float4 v;
    if (kind == 0)      v = ue[users[b] * DV4 + lane];
    else if (kind == 1) v = ie[pos[b]  * DV4 + lane];
    else                v = ie[neg[b]  * DV4 + lane];
    g_sel[i] = v;
}

// ---------------------------------------------------------------------------
// selection-buffer add: g_sel += cur at gathered rows
// whichdst: buffer that the just-finished spmm wrote (0 -> g_buf1, 1 -> g_buf0)
// ---------------------------------------------------------------------------
__global__ void k_sel_add(const int* __restrict__ users, const int* __restrict__ pos,
                          const int* __restrict__ neg, int whichdst) {
    const float4* __restrict__ cur = whichdst ? g_buf0 : g_buf1;
    int i = blockIdx.x * blockDim.x + threadIdx.x;
    if (i >= 3 * BATCH * DV4) return;
    int lane = i & 15;
    int j = i >> 4;
    int kind = j / BATCH;
    int b = j - kind * BATCH;
    int row;
    if (kind == 0)      row = users[b];
    else if (kind == 1) row = NU + pos[b];
    else                row = NU + neg[b];
    float4 v = cur[row * DV4 + lane];
    float4 s = g_sel[i];
    s.x += v.x; s.y += v.y; s.z += v.z; s.w += v.w;
    g_sel[i] = s;
}

// ---------------------------------------------------------------------------
// loss: one warp per batch element.
// g_sel holds acc (= sum of 4 layer outputs); light_out = acc/4, so each
// dot product gets scaled by 1/16.
// ---------------------------------------------------------------------------
__global__ void k_loss(const float2* __restrict__ ue2, const float2* __restrict__ ie2,
                       const int* __restrict__ users, const int* __restrict__ pos,
                       const int* __restrict__ neg, float* __restrict__ out) {
    int t = blockIdx.x * blockDim.x + threadIdx.x;
    int b = t >> 5;
    int lane = t & 31;
    if (b >= BATCH) return;

    const float2* sel2 = (const float2*)g_sel;
    float2 u = sel2[(0 * BATCH + b) * 32 + lane];
    float2 p = sel2[(1 * BATCH + b) * 32 + lane];
    float2 n = sel2[(2 * BATCH + b) * 32 + lane];

    float ps = u.x * p.x + u.y * p.y;
    float ns = u.x * n.x + u.y * n.y;

    float2 uo = ue2[users[b] * 32 + lane];
    float2 po = ie2[pos[b]  * 32 + lane];
    float2 no = ie2[neg[b]  * 32 + lane];
    float rg = uo.x * uo.x + uo.y * uo.y
             + po.x * po.x + po.y * po.y
             + no.x * no.x + no.y * no.y;

    #pragma unroll
    for (int o = 16; o; o >>= 1) {
        ps += __shfl_xor_sync(0xffffffffu, ps, o);
        ns += __shfl_xor_sync(0xffffffffu, ns, o);
        rg += __shfl_xor_sync(0xffffffffu, rg, o);
    }

    if (lane == 0) {
        float x = (ns - ps) * 0.0625f;  // (acc/4)·(acc/4) scale
        float sp = fmaxf(x, 0.0f) + log1pf(expf(-fabsf(x)));
        float contrib = sp * (1.0f / BATCH) + WD * 0.5f * rg * (1.0f / BATCH);
        atomicAdd(out, contrib);
    }
}

// ---------------------------------------------------------------------------
// launch
// inputs: 0 user_emb, 1 item_emb, 2 graph_rows, 3 graph_cols, 4 graph_vals,
//         5 users, 6 positive_items, 7 negative_items
// ---------------------------------------------------------------------------
extern "C" void kernel_launch(void* const* d_in, const int* in_sizes, int n_in,
                              void* d_out, int out_size) {
    const float* ue  = (const float*)d_in[0];
    const float* ie  = (const float*)d_in[1];
    const int*  rows = (const int*)d_in[2];
    const int*  cols = (const int*)d_in[3];
    const float* vals = (const float*)d_in[4];
    const int*  users = (const int*)d_in[5];
    const int*  pos   = (const int*)d_in[6];
    const int*  neg   = (const int*)d_in[7];
    float* out = (float*)d_out;
    int nnz = in_sizes[2];

    const int THR = 256;
    const int SEL_BLOCKS = (3 * BATCH * DV4 + THR - 1) / THR;

    k_init<<<4096, THR>>>((const float4*)ue, (const float4*)ie, out);
    k_sel_init<<<SEL_BLOCKS, THR>>>((const float4*)ue, (const float4*)ie, users, pos, neg);

    // layer 1: buf0 -> buf1
    k_zero<<<4096, THR>>>(0);
    k_spmm<<<8192, THR>>>(rows, cols, vals, nnz, 0);
    k_sel_add<<<SEL_BLOCKS, THR>>>(users, pos, neg, 0);

    // layer 2: buf1 -> buf0
    k_zero<<<4096, THR>>>(1);
    k_spmm<<<8192, THR>>>(rows, cols, vals, nnz, 1);
    k_sel_add<<<SEL_BLOCKS, THR>>>(users, pos, neg, 1);

    // layer 3: buf0 -> buf1
    k_zero<<<4096, THR>>>(0);
    k_spmm<<<8192, THR>>>(rows, cols, vals, nnz, 0);
    k_sel_add<<<SEL_BLOCKS, THR>>>(users, pos, neg, 0);

    k_loss<<<(BATCH * 32 + THR - 1) / THR, THR>>>(
        (const float2*)ue, (const float2*)ie, users, pos, neg, out);
}

// round 2
// speedup vs baseline: 2.0555x; 2.0555x over previous
#include <cuda_runtime.h>

// Problem constants (fixed by the reference)
#define NU    100000
#define NI    50000
#define NTOT  150000
#define D     64
#define DV4   16            // 64 floats = 16 float4
#define BATCH 4096
#define NNZ_MAX 4000000
#define WD    1e-4f

#define SCAN_BLK 1024
#define NBLK ((NTOT + SCAN_BLK - 1) / SCAN_BLK)   // 147

// Scratch (device globals: allocation-free)
__device__ float4 g_buf0[NTOT * DV4];        // 38.4 MB
__device__ float4 g_buf1[NTOT * DV4];        // 38.4 MB
__device__ float4 g_sel[3 * BATCH * DV4];    // gathered acc (3 MB)
__device__ int    g_count[NTOT];
__device__ int    g_rowstart[NTOT];
__device__ int    g_cursor[NTOT];
__device__ int    g_bsum[NBLK];
__device__ int    g_boff[NBLK];
__device__ int2   g_edges[NNZ_MAX];          // {col, val_bits} sorted by row (32 MB)

// ---------------------------------------------------------------------------
// init: g_buf0 = concat(user_emb, item_emb); zero counts; zero d_out
// ---------------------------------------------------------------------------
__global__ void k_init(const float4* __restrict__ ue, const float4* __restrict__ ie,
                       float* __restrict__ out) {
    int gid = blockIdx.x * blockDim.x + threadIdx.x;
    int stride = gridDim.x * blockDim.x;
    if (gid == 0) out[0] = 0.0f;
    for (int j = gid; j < NTOT; j += stride) g_count[j] = 0;
    const int total = NTOT * DV4;
    for (int i = gid; i < total; i += stride)
        g_buf0[i] = (i < NU * DV4) ? ue[i] : ie[i - NU * DV4];
}

// ---------------------------------------------------------------------------
// CSR build: histogram -> scan -> scatter
// ---------------------------------------------------------------------------
__global__ void k_hist(const int* __restrict__ rows, int nnz) {
    int gid = blockIdx.x * blockDim.x + threadIdx.x;
    int stride = gridDim.x * blockDim.x;
    for (int e = gid; e < nnz; e += stride)
        atomicAdd(&g_count[rows[e]], 1);
}

__global__ void k_scanA() {
    __shared__ int sh[SCAN_BLK];
    int tid = threadIdx.x;
    int i = blockIdx.x * SCAN_BLK + tid;
    int v = (i < NTOT) ? g_count[i] : 0;
    sh[tid] = v;
    __syncthreads();
    #pragma unroll
    for (int off = 1; off < SCAN_BLK; off <<= 1) {
        int t = (tid >= off) ? sh[tid - off] : 0;
        __syncthreads();
        sh[tid] += t;
        __syncthreads();
    }
    int inc = sh[tid];
    if (i < NTOT) g_rowstart[i] = inc - v;     // exclusive within block
    if (tid == SCAN_BLK - 1) g_bsum[blockIdx.x] = inc;
}

__global__ void k_scanB() {
    if (threadIdx.x == 0) {
        int s = 0;
        for (int b = 0; b < NBLK; b++) { int t = g_bsum[b]; g_boff[b] = s; s += t; }
    }
}

__global__ void k_scanC() {
    int i = blockIdx.x * blockDim.x + threadIdx.x;
    if (i < NTOT) {
        int s = g_rowstart[i] + g_boff[i >> 10];
        g_rowstart[i] = s;
        g_cursor[i] = s;
    }
}

__global__ void k_scatter(const int* __restrict__ rows, const int* __restrict__ cols,
                          const float* __restrict__ vals, int nnz) {
    int gid = blockIdx.x * blockDim.x + threadIdx.x;
    int stride = gridDim.x * blockDim.x;
    for (int e = gid; e < nnz; e += stride) {
        int r = rows[e];
        int p = atomicAdd(&g_cursor[r], 1);
        g_edges[p] = make_int2(cols[e], __float_as_int(vals[e]));
    }
}

// ---------------------------------------------------------------------------
// CSR SpMM: dst[r] = sum_e vals[e] * src[cols[e]]  (16 lanes per row, reg acc)
// which==0: src=g_buf0, dst=g_buf1 ; which==1: src=g_buf1, dst=g_buf0
// ---------------------------------------------------------------------------
__global__ void k_spmm_csr(int which) {
    const float4* __restrict__ src = which ? g_buf1 : g_buf0;
    float4* dst = which ? g_buf0 : g_buf1;

    int gid = blockIdx.x * blockDim.x + threadIdx.x;
    int lane = gid & 15;
    int r = gid >> 4;
    if (r >= NTOT) return;

    int s = g_rowstart[r];
    int e = s + g_count[r];
    float4 acc = make_float4(0.f, 0.f, 0.f, 0.f);
    for (int i = s; i < e; i++) {
        int2 ed = g_edges[i];
        float v = __int_as_float(ed.y);
        float4 x = src[ed.x * DV4 + lane];
        acc.x = fmaf(v, x.x, acc.x);
        acc.y = fmaf(v, x.y, acc.y);
        acc.z = fmaf(v, x.z, acc.z);
        acc.w = fmaf(v, x.w, acc.w);
    }
    dst[r * DV4 + lane] = acc;
}

// ---------------------------------------------------------------------------
// sliced layer-3 SpMM: compute cur3 only at the 3*BATCH selected rows and
// add directly into g_sel.  src = g_buf0 (layer-2 output).
// ---------------------------------------------------------------------------
__global__ void k_spmm_sel(const int* __restrict__ users, const int* __restrict__ pos,
                           const int* __restrict__ neg) {
    int gid = blockIdx.x * blockDim.x + threadIdx.x;
    if (gid >= 3 * BATCH * DV4) return;
    int lane = gid & 15;
    int j = gid >> 4;
    int kind = j / BATCH;
    int b = j - kind * BATCH;
    int row;
    if (kind == 0)      row = users[b];
    else if (kind == 1) row = NU + pos[b];
    else                row = NU + neg[b];

    int s = g_rowstart[row];
    int e = s + g_count[row];
    float4 acc = g_sel[gid];
    for (int i = s; i < e; i++) {
        int2 ed = g_edges[i];
        float v = __int_as_float(ed.y);
        float4 x = g_buf0[ed.x * DV4 + lane];
        acc.x = fmaf(v, x.x, acc.x);
        acc.y = fmaf(v, x.y, acc.y);
        acc.z = fmaf(v, x.z, acc.z);
        acc.w = fmaf(v, x.w, acc.w);
    }
    g_sel[gid] = acc;
}

// ---------------------------------------------------------------------------
// selection-buffer init / add
// ---------------------------------------------------------------------------
__global__ void k_sel_init(const float4* __restrict__ ue, const float4* __restrict__ ie,
                           const int* __restrict__ users, const int* __restrict__ pos,
                           const int* __restrict__ neg) {
    int i = blockIdx.x * blockDim.x + threadIdx.x;
    if (i >= 3 * BATCH * DV4) return;
    int lane = i & 15;
    int j = i >> 4;
    int kind = j / BATCH;
    int b = j - kind * BATCH;
    float4 v;
    if (kind == 0)      v = ue[users[b] * DV4 + lane];
    else if (kind == 1) v = ie[pos[b]  * DV4 + lane];
    else                v = ie[neg[b]  * DV4 + lane];
    g_sel[i] = v;
}

__global__ void k_sel_add(const int* __restrict__ users, const int* __restrict__ pos,
                          const int* __restrict__ neg, int whichdst) {
    const float4* __restrict__ cur = whichdst ? g_buf0 : g_buf1;
    int i = blockIdx.x * blockDim.x + threadIdx.x;
    if (i >= 3 * BATCH * DV4) return;
    int lane = i & 15;
    int j = i >> 4;
    int kind = j / BATCH;
    int b = j - kind * BATCH;
    int row;
    if (kind == 0)      row = users[b];
    else if (kind == 1) row = NU + pos[b];
    else                row = NU + neg[b];
    float4 v = cur[row * DV4 + lane];
    float4 s = g_sel[i];
    s.x += v.x; s.y += v.y; s.z += v.z; s.w += v.w;
    g_sel[i] = s;
}

// ---------------------------------------------------------------------------
// loss: one warp per batch element; g_sel holds acc = sum of 4 layer outputs
// ---------------------------------------------------------------------------
__global__ void k_loss(const float2* __restrict__ ue2, const float2* __restrict__ ie2,
                       const int* __restrict__ users, const int* __restrict__ pos,
                       const int* __restrict__ neg, float* __restrict__ out) {
    int t = blockIdx.x * blockDim.x + threadIdx.x;
    int b = t >> 5;
    int lane = t & 31;
    if (b >= BATCH) return;

    const float2* sel2 = (const float2*)g_sel;
    float2 u = sel2[(0 * BATCH + b) * 32 + lane];
    float2 p = sel2[(1 * BATCH + b) * 32 + lane];
    float2 n = sel2[(2 * BATCH + b) * 32 + lane];

    float ps = u.x * p.x + u.y * p.y;
    float ns = u.x * n.x + u.y * n.y;

    float2 uo = ue2[users[b] * 32 + lane];
    float2 po = ie2[pos[b]  * 32 + lane];
    float2 no = ie2[neg[b]  * 32 + lane];
    float rg = uo.x * uo.x + uo.y * uo.y
             + po.x * po.x + po.y * po.y
             + no.x * no.x + no.y * no.y;

    #pragma unroll
    for (int o = 16; o; o >>= 1) {
        ps += __shfl_xor_sync(0xffffffffu, ps, o);
        ns += __shfl_xor_sync(0xffffffffu, ns, o);
        rg += __shfl_xor_sync(0xffffffffu, rg, o);
    }

    if (lane == 0) {
        float x = (ns - ps) * 0.0625f;     // (acc/4)·(acc/4)
        float sp = fmaxf(x, 0.0f) + log1pf(expf(-fabsf(x)));
        float contrib = sp * (1.0f / BATCH) + WD * 0.5f * rg * (1.0f / BATCH);
        atomicAdd(out, contrib);
    }
}

// ---------------------------------------------------------------------------
// launch
// inputs: 0 user_emb, 1 item_emb, 2 graph_rows, 3 graph_cols, 4 graph_vals,
//         5 users, 6 positive_items, 7 negative_items
// ---------------------------------------------------------------------------
extern "C" void kernel_launch(void* const* d_in, const int* in_sizes, int n_in,
                              void* d_out, int out_size) {
    const float* ue  = (const float*)d_in[0];
    const float* ie  = (const float*)d_in[1];
    const int*  rows = (const int*)d_in[2];
    const int*  cols = (const int*)d_in[3];
    const float* vals = (const float*)d_in[4];
    const int*  users = (const int*)d_in[5];
    const int*  pos   = (const int*)d_in[6];
    const int*  neg   = (const int*)d_in[7];
    float* out = (float*)d_out;
    int nnz = in_sizes[2];

    const int THR = 256;
    const int SEL_BLOCKS = (3 * BATCH * DV4 + THR - 1) / THR;
    const int EDGE_BLOCKS = (nnz + THR - 1) / THR;
    const int ROW_BLOCKS = (NTOT + THR - 1) / THR;
    const int SPMM_BLOCKS = (NTOT * DV4 + THR - 1) / THR;

    // setup + CSR build
    k_init<<<4096, THR>>>((const float4*)ue, (const float4*)ie, out);
    k_hist<<<EDGE_BLOCKS, THR>>>(rows, nnz);
    k_scanA<<<NBLK, SCAN_BLK>>>();
    k_scanB<<<1, 32>>>();
    k_scanC<<<ROW_BLOCKS, THR>>>();
    k_scatter<<<EDGE_BLOCKS, THR>>>(rows, cols, vals, nnz);

    k_sel_init<<<SEL_BLOCKS, THR>>>((const float4*)ue, (const float4*)ie, users, pos, neg);

    // layer 1: buf0 -> buf1 (full)
    k_spmm_csr<<<SPMM_BLOCKS, THR>>>(0);
    k_sel_add<<<SEL_BLOCKS, THR>>>(users, pos, neg, 0);

    // layer 2: buf1 -> buf0 (full)
    k_spmm_csr<<<SPMM_BLOCKS, THR>>>(1);
    k_sel_add<<<SEL_BLOCKS, THR>>>(users, pos, neg, 1);

    // layer 3: sliced to the 3*BATCH selected rows, accumulated into g_sel
    k_spmm_sel<<<SEL_BLOCKS, THR>>>(users, pos, neg);

    k_loss<<<(BATCH * 32 + THR - 1) / THR, THR>>>(
        (const float2*)ue, (const float2*)ie, users, pos, neg, out);
}

// round 3
// speedup vs baseline: 2.3607x; 1.1485x over previous
#include <cuda_runtime.h>
#include <cuda_fp16.h>

// Problem constants (fixed by the reference)
#define NU    100000
#define NI    50000
#define NTOT  150000
#define D     64
#define BATCH 4096
#define NNZ_MAX 4000000
#define WD    1e-4f

#define SCAN_BLK 1024
#define NBLK ((NTOT + SCAN_BLK - 1) / SCAN_BLK)   // 147

// Scratch (device globals: allocation-free)
// fp16 ping-pong layer buffers: one row = 64 halves = 8 float4 (128 B)
__device__ float4 g_h0[NTOT * 8];            // 19.2 MB
__device__ float4 g_h1[NTOT * 8];            // 19.2 MB
__device__ float4 g_sel[3 * BATCH * 16];     // fp32 gathered acc (3 MB)
__device__ int    g_count[NTOT];
__device__ int    g_rowstart[NTOT];
__device__ int    g_cursor[NTOT];
__device__ int    g_bsum[NBLK];
__device__ int    g_boff[NBLK];
__device__ int2   g_edges[NNZ_MAX];          // {col, val_bits} grouped by row (32 MB)

union F4H { float4 f4; __half2 h2[4]; };

// ---------------------------------------------------------------------------
// init: g_h0 = fp16(concat(user_emb, item_emb)); zero counts; zero d_out
// ---------------------------------------------------------------------------
__global__ void k_init(const float2* __restrict__ ue2, const float2* __restrict__ ie2,
                       float* __restrict__ out) {
    int gid = blockIdx.x * blockDim.x + threadIdx.x;
    int stride = gridDim.x * blockDim.x;
    if (gid == 0) out[0] = 0.0f;
    for (int j = gid; j < NTOT; j += stride) g_count[j] = 0;
    __half2* dst = (__half2*)g_h0;
    const int total = NTOT * 32;               // half2 units
    for (int i = gid; i < total; i += stride) {
        int r = i >> 5;
        int h = i & 31;
        float2 f = (r < NU) ? ue2[r * 32 + h] : ie2[(r - NU) * 32 + h];
        dst[i] = __float22half2_rn(f);
    }
}

// ---------------------------------------------------------------------------
// CSR build: histogram -> scan -> scatter
// ---------------------------------------------------------------------------
__global__ void k_hist(const int* __restrict__ rows, int nnz) {
    int gid = blockIdx.x * blockDim.x + threadIdx.x;
    int stride = gridDim.x * blockDim.x;
    for (int e = gid; e < nnz; e += stride)
        atomicAdd(&g_count[rows[e]], 1);
}

__global__ void k_scanA() {
    __shared__ int sh[SCAN_BLK];
    int tid = threadIdx.x;
    int i = blockIdx.x * SCAN_BLK + tid;
    int v = (i < NTOT) ? g_count[i] : 0;
    sh[tid] = v;
    __syncthreads();
    #pragma unroll
    for (int off = 1; off < SCAN_BLK; off <<= 1) {
        int t = (tid >= off) ? sh[tid - off] : 0;
        __syncthreads();
        sh[tid] += t;
        __syncthreads();
    }
    int inc = sh[tid];
    if (i < NTOT) g_rowstart[i] = inc - v;     // exclusive within block
    if (tid == SCAN_BLK - 1) g_bsum[blockIdx.x] = inc;
}

// parallel scan of the 147 block sums (one block, Hillis-Steele in smem)
__global__ void k_scanB() {
    __shared__ int sh[256];
    int tid = threadIdx.x;
    int v = (tid < NBLK) ? g_bsum[tid] : 0;
    sh[tid] = v;
    __syncthreads();
    #pragma unroll
    for (int off = 1; off < 256; off <<= 1) {
        int t = (tid >= off) ? sh[tid - off] : 0;
        __syncthreads();
        sh[tid] += t;
        __syncthreads();
    }
    if (tid < NBLK) g_boff[tid] = sh[tid] - v;   // exclusive
}

__global__ void k_scanC() {
    int i = blockIdx.x * blockDim.x + threadIdx.x;
    if (i < NTOT) {
        int s = g_rowstart[i] + g_boff[i >> 10];
        g_rowstart[i] = s;
        g_cursor[i] = s;
    }
}

__global__ void k_scatter(const int* __restrict__ rows, const int* __restrict__ cols,
                          const float* __restrict__ vals, int nnz) {
    int gid = blockIdx.x * blockDim.x + threadIdx.x;
    int stride = gridDim.x * blockDim.x;
    for (int e = gid; e < nnz; e += stride) {
        int r = rows[e];
        int p = atomicAdd(&g_cursor[r], 1);
        g_edges[p] = make_int2(cols[e], __float_as_int(vals[e]));
    }
}

// ---------------------------------------------------------------------------
// CSR SpMM (fp16 src/dst, fp32 accum): 8 lanes per row, each lane owns 8
// consecutive feature dims (one float4 = 4 half2).
// which==0: src=g_h0, dst=g_h1 ; which==1: src=g_h1, dst=g_h0
// ---------------------------------------------------------------------------
__global__ void k_spmm_h(int which) {
    const float4* __restrict__ src = which ? g_h1 : g_h0;
    float4* dst = which ? g_h0 : g_h1;

    int gid = blockIdx.x * blockDim.x + threadIdx.x;
    int lane = gid & 7;
    int r = gid >> 3;
    if (r >= NTOT) return;

    int s = g_rowstart[r];
    int e = s + g_count[r];
    float a0 = 0.f, a1 = 0.f, a2 = 0.f, a3 = 0.f;
    float a4 = 0.f, a5 = 0.f, a6 = 0.f, a7 = 0.f;
    for (int i = s; i < e; i++) {
        int2 ed = g_edges[i];
        float v = __int_as_float(ed.y);
        F4H raw; raw.f4 = src[ed.x * 8 + lane];
        float2 f0 = __half22float2(raw.h2[0]);
        float2 f1 = __half22float2(raw.h2[1]);
        float2 f2 = __half22float2(raw.h2[2]);
        float2 f3 = __half22float2(raw.h2[3]);
        a0 = fmaf(v, f0.x, a0); a1 = fmaf(v, f0.y, a1);
        a2 = fmaf(v, f1.x, a2); a3 = fmaf(v, f1.y, a3);
        a4 = fmaf(v, f2.x, a4); a5 = fmaf(v, f2.y, a5);
        a6 = fmaf(v, f3.x, a6); a7 = fmaf(v, f3.y, a7);
    }
    F4H outv;
    outv.h2[0] = __float22half2_rn(make_float2(a0, a1));
    outv.h2[1] = __float22half2_rn(make_float2(a2, a3));
    outv.h2[2] = __float22half2_rn(make_float2(a4, a5));
    outv.h2[3] = __float22half2_rn(make_float2(a6, a7));
    dst[r * 8 + lane] = outv.f4;
}

// ---------------------------------------------------------------------------
// sliced layer-3 SpMM: compute cur3 only at the 3*BATCH selected rows and
// add (fp32) directly into g_sel.  src = g_h0 (layer-2 output, fp16).
// ---------------------------------------------------------------------------
__global__ void k_spmm_sel(const int* __restrict__ users, const int* __restrict__ pos,
                           const int* __restrict__ neg) {
    int gid = blockIdx.x * blockDim.x + threadIdx.x;
    if (gid >= 3 * BATCH * 8) return;
    int lane = gid & 7;
    int j = gid >> 3;
    int kind = j / BATCH;
    int b = j - kind * BATCH;
    int row;
    if (kind == 0)      row = users[b];
    else if (kind == 1) row = NU + pos[b];
    else                row = NU + neg[b];

    int s = g_rowstart[row];
    int e = s + g_count[row];
    float4 acc0 = g_sel[j * 16 + lane * 2];
    float4 acc1 = g_sel[j * 16 + lane * 2 + 1];
    for (int i = s; i < e; i++) {
        int2 ed = g_edges[i];
        float v = __int_as_float(ed.y);
        F4H raw; raw.f4 = g_h0[ed.x * 8 + lane];
        float2 f0 = __half22float2(raw.h2[0]);
        float2 f1 = __half22float2(raw.h2[1]);
        float2 f2 = __half22float2(raw.h2[2]);
        float2 f3 = __half22float2(raw.h2[3]);
        acc0.x = fmaf(v, f0.x, acc0.x); acc0.y = fmaf(v, f0.y, acc0.y);
        acc0.z = fmaf(v, f1.x, acc0.z); acc0.w = fmaf(v, f1.y, acc0.w);
        acc1.x = fmaf(v, f2.x, acc1.x); acc1.y = fmaf(v, f2.y, acc1.y);
        acc1.z = fmaf(v, f3.x, acc1.z); acc1.w = fmaf(v, f3.y, acc1.w);
    }
    g_sel[j * 16 + lane * 2]     = acc0;
    g_sel[j * 16 + lane * 2 + 1] = acc1;
}

// ---------------------------------------------------------------------------
// selection-buffer init (fp32 from original inputs) / add (fp16 cur -> fp32)
// ---------------------------------------------------------------------------
__global__ void k_sel_init(const float4* __restrict__ ue, const float4* __restrict__ ie,
                           const int* __restrict__ users, const int* __restrict__ pos,
                           const int* __restrict__ neg) {
    int i = blockIdx.x * blockDim.x + threadIdx.x;
    if (i >= 3 * BATCH * 16) return;
    int lane = i & 15;
    int j = i >> 4;
    int kind = j / BATCH;
    int b = j - kind * BATCH;
    float4 v;
    if (kind == 0)      v = ue[users[b] * 16 + lane];
    else if (kind == 1) v = ie[pos[b]  * 16 + lane];
    else                v = ie[neg[b]  * 16 + lane];
    g_sel[i] = v;
}

__global__ void k_sel_add(const int* __restrict__ users, const int* __restrict__ pos,
                          const int* __restrict__ neg, int whichdst) {
    const __half2* __restrict__ cur = (const __half2*)(whichdst ? g_h0 : g_h1);
    int i = blockIdx.x * blockDim.x + threadIdx.x;
    if (i >= 3 * BATCH * 32) return;          // half2 units
    int h = i & 31;
    int j = i >> 5;
    int kind = j / BATCH;
    int b = j - kind * BATCH;
    int row;
    if (kind == 0)      row = users[b];
    else if (kind == 1) row = NU + pos[b];
    else                row = NU + neg[b];
    float2 v = __half22float2(cur[row * 32 + h]);
    float2* sel2 = (float2*)g_sel;
    float2 s = sel2[j * 32 + h];
    s.x += v.x; s.y += v.y;
    sel2[j * 32 + h] = s;
}

// ---------------------------------------------------------------------------
// loss: one warp per batch element; g_sel holds acc = sum of 4 layer outputs
// ---------------------------------------------------------------------------
__global__ void k_loss(const float2* __restrict__ ue2, const float2* __restrict__ ie2,
                       const int* __restrict__ users, const int* __restrict__ pos,
                       const int* __restrict__ neg, float* __restrict__ out) {
    int t = blockIdx.x * blockDim.x + threadIdx.x;
    int b = t >> 5;
    int lane = t & 31;
    if (b >= BATCH) return;

    const float2* sel2 = (const float2*)g_sel;
    float2 u = sel2[(0 * BATCH + b) * 32 + lane];
    float2 p = sel2[(1 * BATCH + b) * 32 + lane];
    float2 n = sel2[(2 * BATCH + b) * 32 + lane];

    float ps = u.x * p.x + u.y * p.y;
    float ns = u.x * n.x + u.y * n.y;

    float2 uo = ue2[users[b] * 32 + lane];
    float2 po = ie2[pos[b]  * 32 + lane];
    float2 no = ie2[neg[b]  * 32 + lane];
    float rg = uo.x * uo.x + uo.y * uo.y
             + po.x * po.x + po.y * po.y
             + no.x * no.x + no.y * no.y;

    #pragma unroll
    for (int o = 16; o; o >>= 1) {
        ps += __shfl_xor_sync(0xffffffffu, ps, o);
        ns += __shfl_xor_sync(0xffffffffu, ns, o);
        rg += __shfl_xor_sync(0xffffffffu, rg, o);
    }

    if (lane == 0) {
        float x = (ns - ps) * 0.0625f;     // (acc/4)·(acc/4)
        float sp = fmaxf(x, 0.0f) + log1pf(expf(-fabsf(x)));
        float contrib = sp * (1.0f / BATCH) + WD * 0.5f * rg * (1.0f / BATCH);
        atomicAdd(out, contrib);
    }
}

// ---------------------------------------------------------------------------
// launch
// inputs: 0 user_emb, 1 item_emb, 2 graph_rows, 3 graph_cols, 4 graph_vals,
//         5 users, 6 positive_items, 7 negative_items
// ---------------------------------------------------------------------------
extern "C" void kernel_launch(void* const* d_in, const int* in_sizes, int n_in,
                              void* d_out, int out_size) {
    const float* ue  = (const float*)d_in[0];
    const float* ie  = (const float*)d_in[1];
    const int*  rows = (const int*)d_in[2];
    const int*  cols = (const int*)d_in[3];
    const float* vals = (const float*)d_in[4];
    const int*  users = (const int*)d_in[5];
    const int*  pos   = (const int*)d_in[6];
    const int*  neg   = (const int*)d_in[7];
    float* out = (float*)d_out;
    int nnz = in_sizes[2];

    const int THR = 256;
    const int EDGE_BLOCKS = (nnz + THR - 1) / THR;
    const int ROW_BLOCKS = (NTOT + THR - 1) / THR;
    const int SPMM_BLOCKS = (NTOT * 8 + THR - 1) / THR;
    const int SELI_BLOCKS = (3 * BATCH * 16 + THR - 1) / THR;
    const int SELA_BLOCKS = (3 * BATCH * 32 + THR - 1) / THR;
    const int SELS_BLOCKS = (3 * BATCH * 8 + THR - 1) / THR;

    // setup + CSR build
    k_init<<<4096, THR>>>((const float2*)ue, (const float2*)ie, out);
    k_hist<<<EDGE_BLOCKS, THR>>>(rows, nnz);
    k_scanA<<<NBLK, SCAN_BLK>>>();
    k_scanB<<<1, 256>>>();
    k_scanC<<<ROW_BLOCKS, THR>>>();
    k_scatter<<<EDGE_BLOCKS, THR>>>(rows, cols, vals, nnz);

    k_sel_init<<<SELI_BLOCKS, THR>>>((const float4*)ue, (const float4*)ie, users, pos, neg);

    // layer 1: h0 -> h1 (full)
    k_spmm_h<<<SPMM_BLOCKS, THR>>>(0);
    k_sel_add<<<SELA_BLOCKS, THR>>>(users, pos, neg, 0);

    // layer 2: h1 -> h0 (full)
    k_spmm_h<<<SPMM_BLOCKS, THR>>>(1);
    k_sel_add<<<SELA_BLOCKS, THR>>>(users, pos, neg, 1);

    // layer 3: sliced to the 3*BATCH selected rows, accumulated into g_sel
    k_spmm_sel<<<SELS_BLOCKS, THR>>>(users, pos, neg);

    k_loss<<<(BATCH * 32 + THR - 1) / THR, THR>>>(
        (const float2*)ue, (const float2*)ie, users, pos, neg, out);
}

// round 4
// speedup vs baseline: 2.5101x; 1.0633x over previous
#include <cuda_runtime.h>
#include <cuda_fp16.h>

// Problem constants (fixed by the reference)
#define NU    100000
#define NI    50000
#define NTOT  150000
#define BATCH 4096
#define NNZ_MAX 4000000
#define WD    1e-4f

#define SCAN_BLK 1024
#define NSCAN ((NTOT + SCAN_BLK - 1) / SCAN_BLK)   // 147

#define FLAG_INC 0x80000000u
#define FLAG_AGG 0x40000000u
#define VALMASK  0x3FFFFFFFu

#define THR 256
#define SPMM_BLOCKS ((NTOT * 8 + THR - 1) / THR)          // 4688
#define SELA_BLOCKS ((3 * BATCH * 8 + THR - 1) / THR)     // 384
#define SELI_COUNT  (3 * BATCH * 16)
#define LOSS_BLOCKS ((BATCH * 32 + THR - 1) / THR)        // 512
#define ZERO_BLOCKS ((NTOT + THR - 1) / THR)              // 586

// Scratch (device globals: allocation-free, zero-initialized at load)
__device__ float4   g_h0[NTOT * 8];          // fp16 layer buf (19.2 MB)
__device__ float4   g_h1[NTOT * 8];          // fp16 layer buf (19.2 MB)
__device__ float4   g_sel[3 * BATCH * 16];   // fp32 gathered acc (3 MB)
__device__ int      g_count[NTOT];
__device__ int      g_rowstart[NTOT + 1];
__device__ int      g_cursor[NTOT];
__device__ unsigned g_spine[NSCAN];
__device__ int2     g_edges[NNZ_MAX];        // {col, val_bits} grouped by row

union F4H { float4 f4; __half2 h2[4]; };

// ---------------------------------------------------------------------------
// setup: block-partitioned [hist | init g_h0 | sel_init]; zero d_out.
// Requires g_count == 0 on entry (module load or previous call's loss_fin).
// ---------------------------------------------------------------------------
__global__ void k_setup(const float2* __restrict__ ue2, const float2* __restrict__ ie2,
                        const float4* __restrict__ ue4, const float4* __restrict__ ie4,
                        const int* __restrict__ rows, int nnz,
                        const int* __restrict__ users, const int* __restrict__ pos,
                        const int* __restrict__ neg, float* __restrict__ out,
                        int histBlocks, int initBlocks) {
    int b = blockIdx.x;
    if (b == 0 && threadIdx.x == 0) out[0] = 0.0f;

    if (b < histBlocks) {
        int t = b * THR + threadIdx.x;
        int base = t * 4;
        if (base + 3 < nnz) {
            int4 r4 = *(const int4*)(rows + base);
            atomicAdd(&g_count[r4.x], 1);
            atomicAdd(&g_count[r4.y], 1);
            atomicAdd(&g_count[r4.z], 1);
            atomicAdd(&g_count[r4.w], 1);
        } else {
            for (int e = base; e < nnz; e++) atomicAdd(&g_count[rows[e]], 1);
        }
    } else if (b < histBlocks + initBlocks) {
        int t = (b - histBlocks) * THR + threadIdx.x;
        int stride = initBlocks * THR;
        __half2* dst = (__half2*)g_h0;
        const int total = NTOT * 32;          // half2 units
        for (int i = t; i < total; i += stride) {
            int r = i >> 5;
            int h = i & 31;
            float2 f = (r < NU) ? ue2[r * 32 + h] : ie2[(r - NU) * 32 + h];
            dst[i] = __float22half2_rn(f);
        }
    } else {
        int t = (b - histBlocks - initBlocks) * THR + threadIdx.x;
        if (t >= SELI_COUNT) return;
        int lane = t & 15;
        int j = t >> 4;
        int kind = j / BATCH;
        int bb = j - kind * BATCH;
        float4 v;
        if (kind == 0)      v = ue4[users[bb] * 16 + lane];
        else if (kind == 1) v = ie4[pos[bb]  * 16 + lane];
        else                v = ie4[neg[bb]  * 16 + lane];
        g_sel[t] = v;
    }
}

// ---------------------------------------------------------------------------
// single-pass exclusive scan over g_count (decoupled lookback).
// 147 blocks, all resident on 148 SMs. Requires g_spine == 0 on entry.
// Writes g_rowstart[0..NTOT] and g_cursor.
// ---------------------------------------------------------------------------
__global__ void __launch_bounds__(SCAN_BLK) k_scan() {
    __shared__ int warpsum[32];
    __shared__ int s_prefix;
    int b = blockIdx.x, tid = threadIdx.x;
    int lane = tid & 31, wid = tid >> 5;
    int i = b * SCAN_BLK + tid;
    int v = (i < NTOT) ? g_count[i] : 0;

    int x = v;
    #pragma unroll
    for (int o = 1; o < 32; o <<= 1) {
        int y = __shfl_up_sync(0xffffffffu, x, o);
        if (lane >= o) x += y;
    }
    if (lane == 31) warpsum[wid] = x;
    __syncthreads();
    if (wid == 0) {
        int w = warpsum[lane];
        #pragma unroll
        for (int o = 1; o < 32; o <<= 1) {
            int y = __shfl_up_sync(0xffffffffu, w, o);
            if (lane >= o) w += y;
        }
        warpsum[lane] = w;
    }
    __syncthreads();
    int incl = x + (wid ? warpsum[wid - 1] : 0);
    int agg = warpsum[31];

    if (tid == 0) {
        if (b == 0) {
            atomicExch(&g_spine[0], (unsigned)agg | FLAG_INC);
            s_prefix = 0;
        } else {
            atomicExch(&g_spine[b], (unsigned)agg | FLAG_AGG);
            int pb = b - 1;
            unsigned pref = 0;
            while (true) {
                unsigned s = atomicAdd(&g_spine[pb], 0u);
                if (s & FLAG_INC) { pref += s & VALMASK; break; }
                if (s & FLAG_AGG) { pref += s & VALMASK; pb--; }
            }
            atomicExch(&g_spine[b], ((unsigned)agg + pref) | FLAG_INC);
            s_prefix = (int)pref;
        }
    }
    __syncthreads();
    int excl = s_prefix + incl - v;
    if (i < NTOT) { g_rowstart[i] = excl; g_cursor[i] = excl; }
    if (i == NTOT - 1) g_rowstart[NTOT] = excl + v;
}

// ---------------------------------------------------------------------------
// scatter edges into row-grouped order (4 edges per thread)
// ---------------------------------------------------------------------------
__global__ void k_scatter(const int* __restrict__ rows, const int* __restrict__ cols,
                          const float* __restrict__ vals, int nnz) {
    int t = blockIdx.x * THR + threadIdx.x;
    int base = t * 4;
    if (base + 3 < nnz) {
        int4 r = *(const int4*)(rows + base);
        int4 c = *(const int4*)(cols + base);
        float4 v = *(const float4*)(vals + base);
        int p0 = atomicAdd(&g_cursor[r.x], 1);
        int p1 = atomicAdd(&g_cursor[r.y], 1);
        int p2 = atomicAdd(&g_cursor[r.z], 1);
        int p3 = atomicAdd(&g_cursor[r.w], 1);
        g_edges[p0] = make_int2(c.x, __float_as_int(v.x));
        g_edges[p1] = make_int2(c.y, __float_as_int(v.y));
        g_edges[p2] = make_int2(c.z, __float_as_int(v.z));
        g_edges[p3] = make_int2(c.w, __float_as_int(v.w));
    } else {
        for (int e = base; e < nnz; e++) {
            int p = atomicAdd(&g_cursor[rows[e]], 1);
            g_edges[p] = make_int2(cols[e], __float_as_int(vals[e]));
        }
    }
}

// ---------------------------------------------------------------------------
// CSR SpMM body (fp16 src/dst, fp32 accum): 8 lanes/row, unrolled x2.
// ---------------------------------------------------------------------------
__device__ __forceinline__ void spmm_row(const float4* __restrict__ src,
                                         float4* __restrict__ dst,
                                         int r, int lane) {
    int s = g_rowstart[r];
    int e = g_rowstart[r + 1];
    float a0 = 0.f, a1 = 0.f, a2 = 0.f, a3 = 0.f;
    float a4 = 0.f, a5 = 0.f, a6 = 0.f, a7 = 0.f;
    int i = s;
    for (; i + 1 < e; i += 2) {
        int2 e0 = g_edges[i];
        int2 e1 = g_edges[i + 1];
        float v0 = __int_as_float(e0.y);
        float v1 = __int_as_float(e1.y);
        F4H raw0; raw0.f4 = src[e0.x * 8 + lane];
        F4H raw1; raw1.f4 = src[e1.x * 8 + lane];
        float2 f0 = __half22float2(raw0.h2[0]);
        float2 f1 = __half22float2(raw0.h2[1]);
        float2 f2 = __half22float2(raw0.h2[2]);
        float2 f3 = __half22float2(raw0.h2[3]);
        a0 = fmaf(v0, f0.x, a0); a1 = fmaf(v0, f0.y, a1);
        a2 = fmaf(v0, f1.x, a2); a3 = fmaf(v0, f1.y, a3);
        a4 = fmaf(v0, f2.x, a4); a5 = fmaf(v0, f2.y, a5);
        a6 = fmaf(v0, f3.x, a6); a7 = fmaf(v0, f3.y, a7);
        f0 = __half22float2(raw1.h2[0]);
        f1 = __half22float2(raw1.h2[1]);
        f2 = __half22float2(raw1.h2[2]);
        f3 = __half22float2(raw1.h2[3]);
        a0 = fmaf(v1, f0.x, a0); a1 = fmaf(v1, f0.y, a1);
        a2 = fmaf(v1, f1.x, a2); a3 = fmaf(v1, f1.y, a3);
        a4 = fmaf(v1, f2.x, a4); a5 = fmaf(v1, f2.y, a5);
        a6 = fmaf(v1, f3.x, a6); a7 = fmaf(v1, f3.y, a7);
    }
    if (i < e) {
        int2 ed = g_edges[i];
        float v = __int_as_float(ed.y);
        F4H raw; raw.f4 = src[ed.x * 8 + lane];
        float2 f0 = __half22float2(raw.h2[0]);
        float2 f1 = __half22float2(raw.h2[1]);
        float2 f2 = __half22float2(raw.h2[2]);
        float2 f3 = __half22float2(raw.h2[3]);
        a0 = fmaf(v, f0.x, a0); a1 = fmaf(v, f0.y, a1);
        a2 = fmaf(v, f1.x, a2); a3 = fmaf(v, f1.y, a3);
        a4 = fmaf(v, f2.x, a4); a5 = fmaf(v, f2.y, a5);
        a6 = fmaf(v, f3.x, a6); a7 = fmaf(v, f3.y, a7);
    }
    F4H outv;
    outv.h2[0] = __float22half2_rn(make_float2(a0, a1));
    outv.h2[1] = __float22half2_rn(make_float2(a2, a3));
    outv.h2[2] = __float22half2_rn(make_float2(a4, a5));
    outv.h2[3] = __float22half2_rn(make_float2(a6, a7));
    dst[r * 8 + lane] = outv.f4;
}

// layer 1: g_h0 -> g_h1
__global__ void __launch_bounds__(THR) k_spmm1() {
    int gid = blockIdx.x * THR + threadIdx.x;
    int lane = gid & 7;
    int r = gid >> 3;
    if (r >= NTOT) return;
    spmm_row(g_h0, g_h1, r, lane);
}

// shared helper: selected-row index
__device__ __forceinline__ int sel_row(int j, const int* __restrict__ users,
                                       const int* __restrict__ pos,
                                       const int* __restrict__ neg) {
    int kind = j / BATCH;
    int b = j - kind * BATCH;
    if (kind == 0) return users[b];
    if (kind == 1) return NU + pos[b];
    return NU + neg[b];
}

// layer 2 (g_h1 -> g_h0) fused with sel_add of cur1 (g_h1 -> g_sel)
__global__ void __launch_bounds__(THR) k_layer2(const int* __restrict__ users,
                                                const int* __restrict__ pos,
                                                const int* __restrict__ neg) {
    if (blockIdx.x < SPMM_BLOCKS) {
        int gid = blockIdx.x * THR + threadIdx.x;
        int lane = gid & 7;
        int r = gid >> 3;
        if (r >= NTOT) return;
        spmm_row(g_h1, g_h0, r, lane);
    } else {
        int t = (blockIdx.x - SPMM_BLOCKS) * THR + threadIdx.x;
        if (t >= 3 * BATCH * 8) return;
        int lane = t & 7;
        int j = t >> 3;
        int row = sel_row(j, users, pos, neg);
        F4H raw; raw.f4 = g_h1[row * 8 + lane];
        float2 f0 = __half22float2(raw.h2[0]);
        float2 f1 = __half22float2(raw.h2[1]);
        float2 f2 = __half22float2(raw.h2[2]);
        float2 f3 = __half22float2(raw.h2[3]);
        float4 s0 = g_sel[j * 16 + lane * 2];
        float4 s1 = g_sel[j * 16 + lane * 2 + 1];
        s0.x += f0.x; s0.y += f0.y; s0.z += f1.x; s0.w += f1.y;
        s1.x += f2.x; s1.y += f2.y; s1.z += f3.x; s1.w += f3.y;
        g_sel[j * 16 + lane * 2]     = s0;
        g_sel[j * 16 + lane * 2 + 1] = s1;
    }
}

// sel_add of cur2 (g_h0) + sliced layer-3 SpMM into g_sel
__global__ void __launch_bounds__(THR) k_sel23(const int* __restrict__ users,
                                               const int* __restrict__ pos,
                                               const int* __restrict__ neg) {
    int gid = blockIdx.x * THR + threadIdx.x;
    if (gid >= 3 * BATCH * 8) return;
    int lane = gid & 7;
    int j = gid >> 3;
    int row = sel_row(j, users, pos, neg);

    float4 acc0 = g_sel[j * 16 + lane * 2];
    float4 acc1 = g_sel[j * 16 + lane * 2 + 1];

    // + cur2[row]
    {
        F4H raw; raw.f4 = g_h0[row * 8 + lane];
        float2 f0 = __half22float2(raw.h2[0]);
        float2 f1 = __half22float2(raw.h2[1]);
        float2 f2 = __half22float2(raw.h2[2]);
        float2 f3 = __half22float2(raw.h2[3]);
        acc0.x += f0.x; acc0.y += f0.y; acc0.z += f1.x; acc0.w += f1.y;
        acc1.x += f2.x; acc1.y += f2.y; acc1.z += f3.x; acc1.w += f3.y;
    }
    // + cur3[row] = sum over edges of row
    int s = g_rowstart[row];
    int e = g_rowstart[row + 1];
    for (int i = s; i < e; i++) {
        int2 ed = g_edges[i];
        float v = __int_as_float(ed.y);
        F4H raw; raw.f4 = g_h0[ed.x * 8 + lane];
        float2 f0 = __half22float2(raw.h2[0]);
        float2 f1 = __half22float2(raw.h2[1]);
        float2 f2 = __half22float2(raw.h2[2]);
        float2 f3 = __half22float2(raw.h2[3]);
        acc0.x = fmaf(v, f0.x, acc0.x); acc0.y = fmaf(v, f0.y, acc0.y);
        acc0.z = fmaf(v, f1.x, acc0.z); acc0.w = fmaf(v, f1.y, acc0.w);
        acc1.x = fmaf(v, f2.x, acc1.x); acc1.y = fmaf(v, f2.y, acc1.y);
        acc1.z = fmaf(v, f3.x, acc1.z); acc1.w = fmaf(v, f3.y, acc1.w);
    }
    g_sel[j * 16 + lane * 2]     = acc0;
    g_sel[j * 16 + lane * 2 + 1] = acc1;
}

// ---------------------------------------------------------------------------
// loss + scratch re-zero (self-restoring state for the next call/replay)
// ---------------------------------------------------------------------------
__global__ void __launch_bounds__(THR) k_loss_fin(
        const float2* __restrict__ ue2, const float2* __restrict__ ie2,
        const int* __restrict__ users, const int* __restrict__ pos,
        const int* __restrict__ neg, float* __restrict__ out) {
    if (blockIdx.x >= LOSS_BLOCKS) {
        int t = (blockIdx.x - LOSS_BLOCKS) * THR + threadIdx.x;
        if (t < NTOT) g_count[t] = 0;
        if (t < NSCAN) g_spine[t] = 0u;
        return;
    }
    int t = blockIdx.x * THR + threadIdx.x;
    int b = t >> 5;
    int lane = t & 31;
    if (b >= BATCH) return;

    const float2* sel2 = (const float2*)g_sel;
    float2 u = sel2[(0 * BATCH + b) * 32 + lane];
    float2 p = sel2[(1 * BATCH + b) * 32 + lane];
    float2 n = sel2[(2 * BATCH + b) * 32 + lane];

    float ps = u.x * p.x + u.y * p.y;
    float ns = u.x * n.x + u.y * n.y;

    float2 uo = ue2[users[b] * 32 + lane];
    float2 po = ie2[pos[b]  * 32 + lane];
    float2 no = ie2[neg[b]  * 32 + lane];
    float rg = uo.x * uo.x + uo.y * uo.y
             + po.x * po.x + po.y * po.y
             + no.x * no.x + no.y * no.y;

    #pragma unroll
    for (int o = 16; o; o >>= 1) {
        ps += __shfl_xor_sync(0xffffffffu, ps, o);
        ns += __shfl_xor_sync(0xffffffffu, ns, o);
        rg += __shfl_xor_sync(0xffffffffu, rg, o);
    }

    if (lane == 0) {
        float x = (ns - ps) * 0.0625f;     // (acc/4)·(acc/4)
        float sp = fmaxf(x, 0.0f) + log1pf(expf(-fabsf(x)));
        float contrib = sp * (1.0f / BATCH) + WD * 0.5f * rg * (1.0f / BATCH);
        atomicAdd(out, contrib);
    }
}

// ---------------------------------------------------------------------------
// launch
// inputs: 0 user_emb, 1 item_emb, 2 graph_rows, 3 graph_cols, 4 graph_vals,
//         5 users, 6 positive_items, 7 negative_items
// ---------------------------------------------------------------------------
extern "C" void kernel_launch(void* const* d_in, const int* in_sizes, int n_in,
                              void* d_out, int out_size) {
    const float* ue  = (const float*)d_in[0];
    const float* ie  = (const float*)d_in[1];
    const int*  rows = (const int*)d_in[2];
    const int*  cols = (const int*)d_in[3];
    const float* vals = (const float*)d_in[4];
    const int*  users = (const int*)d_in[5];
    const int*  pos   = (const int*)d_in[6];
    const int*  neg   = (const int*)d_in[7];
    float* out = (float*)d_out;
    int nnz = in_sizes[2];

    int histBlocks = (nnz + THR * 4 - 1) / (THR * 4);
    int initBlocks = 2048;
    int seliBlocks = (SELI_COUNT + THR - 1) / THR;
    int setupBlocks = histBlocks + initBlocks + seliBlocks;
    int scatBlocks = (nnz + THR * 4 - 1) / (THR * 4);

    k_setup<<<setupBlocks, THR>>>((const float2*)ue, (const float2*)ie,
                                  (const float4*)ue, (const float4*)ie,
                                  rows, nnz, users, pos, neg, out,
                                  histBlocks, initBlocks);
    k_scan<<<NSCAN, SCAN_BLK>>>();
    k_scatter<<<scatBlocks, THR>>>(rows, cols, vals, nnz);

    k_spmm1<<<SPMM_BLOCKS, THR>>>();
    k_layer2<<<SPMM_BLOCKS + SELA_BLOCKS, THR>>>(users, pos, neg);
    k_sel23<<<SELA_BLOCKS, THR>>>(users, pos, neg);

    k_loss_fin<<<LOSS_BLOCKS + ZERO_BLOCKS, THR>>>(
        (const float2*)ue, (const float2*)ie, users, pos, neg, out);
}